// round 7
// baseline (speedup 1.0000x reference)
#include <cuda_runtime.h>
#include <cuda_bf16.h>
#include <cstdint>

// Problem constants
#define NXg 512
#define NYg 512
#define NSENS 128
#define NT 2048
#define NPIX (NXg * NYg)

// Two half-channel scratch arrays: [s][t][4ch], viewed as 2x u64 per (s,t).
// 4 MB each; a 128B line holds 8 consecutive t entries -> low line overfetch.
__device__ unsigned long long g_scratchA[NSENS * NT * 2];   // channels 0..3
__device__ unsigned long long g_scratchB[NSENS * NT * 2];   // channels 4..7

// ---------------------------------------------------------------------------
// Prep kernel: transpose sensor_data [B=4][C=2][S=128][T=2048] -> 2x [S][T][4]
// ---------------------------------------------------------------------------
__global__ __launch_bounds__(256) void das_transpose_kernel(
    const float* __restrict__ sd)
{
    int idx = blockIdx.x * blockDim.x + threadIdx.x;   // 0 .. 128*2048-1
    if (idx >= NSENS * NT) return;
    int s = idx >> 11;
    int t = idx & (NT - 1);

    const int bcStride = NSENS * NT;
    const float* base = sd + s * NT + t;

    float2 p0 = make_float2(base[0 * bcStride], base[1 * bcStride]);
    float2 p1 = make_float2(base[2 * bcStride], base[3 * bcStride]);
    float2 p2 = make_float2(base[4 * bcStride], base[5 * bcStride]);
    float2 p3 = make_float2(base[6 * bcStride], base[7 * bcStride]);

    ((float2*)g_scratchA)[idx * 2 + 0] = p0;
    ((float2*)g_scratchA)[idx * 2 + 1] = p1;
    ((float2*)g_scratchB)[idx * 2 + 0] = p2;
    ((float2*)g_scratchB)[idx * 2 + 1] = p3;
}

// ---------------------------------------------------------------------------
// Main DAS kernel: one thread per pixel, 128-sensor loop.
// Warp covers a compact 8(iy) x 4(ix) patch. Gathers are issued as 4 separate
// LDG.64 (inline asm, un-fusable) so L1 wavefronts pipeline cross-LDG at
// ~1 cyc/wf instead of serializing as within-LDG replays at ~2 cyc/wf.
// ---------------------------------------------------------------------------
__global__ __launch_bounds__(256) void das_main_kernel(
    const int* __restrict__ sensor_xy,   // [128][2] int32
    float* __restrict__ out)             // [8][NPIX]
{
    __shared__ float2 sxy[NSENS];

    const int tid  = threadIdx.x;        // 0..255
    const int lane = tid & 31;
    const int w    = tid >> 5;           // 0..7

    if (tid < NSENS) {
        int2 xy = ((const int2*)sensor_xy)[tid];
        sxy[tid] = make_float2((float)xy.x, (float)xy.y);
    }
    __syncthreads();

    // Warp patch: 8 iy x 4 ix. Warps tile 2x4 over the 16x16 block tile.
    const int ly = lane & 7;
    const int lx = lane >> 3;
    const int wy = w & 1;
    const int wx = w >> 1;

    const int iy = blockIdx.x * 16 + wy * 8 + ly;
    const int ix = blockIdx.y * 16 + wx * 4 + lx;

    const float fix = (float)ix;
    const float fiy = (float)iy;

    // XLA chain (bit-exact, validated R3): dis * fl(fl(1/VS)*fl(1/DT)).
    const float K = (1.0f / 1550.0f) * (1.0f / 2.5e-8f);

    // Packed accumulators (add.rn.f32x2 = two independent IEEE RN adds).
    unsigned long long a0 = 0ull, a1 = 0ull, a2 = 0ull, a3 = 0ull;

    #pragma unroll 8
    for (int s = 0; s < NSENS; ++s) {
        float2 c = sxy[s];
        float dx = __fmul_rn(c.x - fix, 1e-4f);
        float dy = __fmul_rn(c.y - fiy, 1e-4f);
        float r2 = __fadd_rn(__fmul_rn(dx, dx), __fmul_rn(dy, dy));
        float dis = __fsqrt_rn(r2);
        int t = (int)__fmul_rn(dis, K);

        unsigned long long off = (((unsigned)s << 11) + (unsigned)t) * 16ull;
        const char* baseA = (const char*)g_scratchA + off;
        const char* baseB = (const char*)g_scratchB + off;

        unsigned long long v0, v1, v2, v3;
        asm("ld.global.nc.b64 %0, [%1];"     : "=l"(v0) : "l"(baseA));
        asm("ld.global.nc.b64 %0, [%1+8];"   : "=l"(v1) : "l"(baseA));
        asm("ld.global.nc.b64 %0, [%1];"     : "=l"(v2) : "l"(baseB));
        asm("ld.global.nc.b64 %0, [%1+8];"   : "=l"(v3) : "l"(baseB));

        asm("add.rn.f32x2 %0, %0, %1;" : "+l"(a0) : "l"(v0));
        asm("add.rn.f32x2 %0, %0, %1;" : "+l"(a1) : "l"(v1));
        asm("add.rn.f32x2 %0, %0, %1;" : "+l"(a2) : "l"(v2));
        asm("add.rn.f32x2 %0, %0, %1;" : "+l"(a3) : "l"(v3));
    }

    const int p = ix * NYg + iy;
    unsigned lo, hi;
    asm("mov.b64 {%0,%1}, %2;" : "=r"(lo), "=r"(hi) : "l"(a0));
    out[0 * NPIX + p] = __uint_as_float(lo);
    out[1 * NPIX + p] = __uint_as_float(hi);
    asm("mov.b64 {%0,%1}, %2;" : "=r"(lo), "=r"(hi) : "l"(a1));
    out[2 * NPIX + p] = __uint_as_float(lo);
    out[3 * NPIX + p] = __uint_as_float(hi);
    asm("mov.b64 {%0,%1}, %2;" : "=r"(lo), "=r"(hi) : "l"(a2));
    out[4 * NPIX + p] = __uint_as_float(lo);
    out[5 * NPIX + p] = __uint_as_float(hi);
    asm("mov.b64 {%0,%1}, %2;" : "=r"(lo), "=r"(hi) : "l"(a3));
    out[6 * NPIX + p] = __uint_as_float(lo);
    out[7 * NPIX + p] = __uint_as_float(hi);
}

// ---------------------------------------------------------------------------
// Entry point
// ---------------------------------------------------------------------------
extern "C" void kernel_launch(void* const* d_in, const int* in_sizes, int n_in,
                              void* d_out, int out_size)
{
    const float* sensor_data = (const float*)d_in[0];   // (4,2,128,2048) f32
    const int*   sensor_xy   = (const int*)d_in[1];     // (128,2) i32
    float*       out         = (float*)d_out;           // (4,2,512,512) f32

    das_transpose_kernel<<<(NSENS * NT + 255) / 256, 256>>>(sensor_data);

    dim3 block(256);
    dim3 grid(NYg / 16, NXg / 16);
    das_main_kernel<<<grid, block>>>(sensor_xy, out);
}

// round 8
// speedup vs baseline: 1.0929x; 1.0929x over previous
#include <cuda_runtime.h>
#include <cuda_bf16.h>
#include <cstdint>

// Problem constants
#define NXg 512
#define NYg 512
#define NSENS 128
#define NT 2048
#define NPIX (NXg * NYg)

#define GROUP 8        // sensors staged per round
#define ROUNDS (NSENS / GROUP)
#define WWIN 60        // window entries per (block,sensor); true span <= 56
#define ESTR 9         // words per entry: 8 data + 1 pad -> bank period 32

// Scratch: sensor data transposed to [s][t][8ch] (32B entries). 8 MB.
__device__ float4 g_scratch[NSENS * NT * 2];

// ---------------------------------------------------------------------------
// Prep kernel: transpose sensor_data [B=4][C=2][S=128][T=2048] -> [S][T][8]
// ---------------------------------------------------------------------------
__global__ __launch_bounds__(256) void das_transpose_kernel(
    const float* __restrict__ sd)
{
    int idx = blockIdx.x * blockDim.x + threadIdx.x;   // 0 .. 128*2048-1
    if (idx >= NSENS * NT) return;
    int s = idx >> 11;
    int t = idx & (NT - 1);

    const int bcStride = NSENS * NT;
    const float* base = sd + s * NT + t;

    float4 v0, v1;
    v0.x = base[0 * bcStride];
    v0.y = base[1 * bcStride];
    v0.z = base[2 * bcStride];
    v0.w = base[3 * bcStride];
    v1.x = base[4 * bcStride];
    v1.y = base[5 * bcStride];
    v1.z = base[6 * bcStride];
    v1.w = base[7 * bcStride];

    g_scratch[idx * 2 + 0] = v0;
    g_scratch[idx * 2 + 1] = v1;
}

// ---------------------------------------------------------------------------
// Main DAS kernel: 16x16 pixel tile per block; per round of 8 sensors, stage
// each sensor's 60-entry delay window into smem (36B-padded entries,
// conflict-free for warp t-span < 32), then gather via 8x LDS.32.
// ---------------------------------------------------------------------------
__global__ __launch_bounds__(256) void das_main_kernel(
    const int* __restrict__ sensor_xy,   // [128][2] int32
    float* __restrict__ out)             // [8][NPIX]
{
    __shared__ float4 smeta[NSENS];                  // cx, cy, tmin(bits), -
    __shared__ float  swin[GROUP * WWIN * ESTR];     // 17280 B

    const int tid  = threadIdx.x;        // 0..255
    const int lane = tid & 31;
    const int w    = tid >> 5;

    const int iy0 = blockIdx.x * 16;
    const int ix0 = blockIdx.y * 16;

    // XLA chain (bit-exact, validated R3): dis * fl(fl(1/VS)*fl(1/DT)).
    const float K = (1.0f / 1550.0f) * (1.0f / 2.5e-8f);

    // Per-sensor meta: position + window base. tmin is t at the clamped
    // projection of the sensor onto the tile, computed through the SAME
    // monotone RN chain => tmin <= t(pixel) for all tile pixels (R4-validated).
    if (tid < NSENS) {
        int2 xy = ((const int2*)sensor_xy)[tid];
        float cx = (float)xy.x, cy = (float)xy.y;
        float px = fminf(fmaxf(cx, (float)ix0), (float)(ix0 + 15));
        float py = fminf(fmaxf(cy, (float)iy0), (float)(iy0 + 15));
        float dx = __fmul_rn(cx - px, 1e-4f);
        float dy = __fmul_rn(cy - py, 1e-4f);
        float dis = __fsqrt_rn(__fadd_rn(__fmul_rn(dx, dx), __fmul_rn(dy, dy)));
        int tmin = (int)__fmul_rn(dis, K);           // tmin + 59 < 2048 always
        smeta[tid] = make_float4(cx, cy, __int_as_float(tmin), 0.0f);
    }

    // Warp patch: 8 iy x 4 ix (t-span <= 21 per warp => conflict-free LDS).
    const int ly = lane & 7;
    const int lx = lane >> 3;
    const int wy = w & 1;
    const int wx = w >> 1;
    const int iy = iy0 + wy * 8 + ly;
    const int ix = ix0 + wx * 4 + lx;
    const float fix = (float)ix;
    const float fiy = (float)iy;

    float a0 = 0.f, a1 = 0.f, a2 = 0.f, a3 = 0.f;
    float a4 = 0.f, a5 = 0.f, a6 = 0.f, a7 = 0.f;

    __syncthreads();   // smeta ready

    for (int r = 0; r < ROUNDS; ++r) {
        // ---- Stage GROUP windows: GROUP*WWIN entries, 2 float4 each ----
        #pragma unroll
        for (int it = 0; it < 4; ++it) {
            int f = tid + it * 256;                  // 0..959 (last iter partial)
            if (f < GROUP * WWIN * 2) {
                int g   = f / (WWIN * 2);
                int rem = f - g * (WWIN * 2);
                int e   = rem >> 1;
                int h   = rem & 1;
                int s   = r * GROUP + g;
                int tmn = __float_as_int(smeta[s].z);
                float4 v = g_scratch[((((unsigned)s << 11) + (unsigned)(tmn + e)) << 1) + h];
                int wb = (g * WWIN + e) * ESTR + (h << 2);
                swin[wb + 0] = v.x;
                swin[wb + 1] = v.y;
                swin[wb + 2] = v.z;
                swin[wb + 3] = v.w;
            }
        }
        __syncthreads();   // windows visible

        // ---- Gather 8 sensors from smem ----
        #pragma unroll
        for (int g = 0; g < GROUP; ++g) {
            int s = r * GROUP + g;
            float4 m = smeta[s];                     // LDS.128 broadcast
            float dx = __fmul_rn(m.x - fix, 1e-4f);
            float dy = __fmul_rn(m.y - fiy, 1e-4f);
            float dis = __fsqrt_rn(__fadd_rn(__fmul_rn(dx, dx), __fmul_rn(dy, dy)));
            int t = (int)__fmul_rn(dis, K);
            int tloc = t - __float_as_int(m.z);
            int wb = (g * WWIN + tloc) * ESTR;

            a0 += swin[wb + 0];
            a1 += swin[wb + 1];
            a2 += swin[wb + 2];
            a3 += swin[wb + 3];
            a4 += swin[wb + 4];
            a5 += swin[wb + 5];
            a6 += swin[wb + 6];
            a7 += swin[wb + 7];
        }
        __syncthreads();   // gathers done before next round overwrites
    }

    const int p = ix * NYg + iy;
    out[0 * NPIX + p] = a0;
    out[1 * NPIX + p] = a1;
    out[2 * NPIX + p] = a2;
    out[3 * NPIX + p] = a3;
    out[4 * NPIX + p] = a4;
    out[5 * NPIX + p] = a5;
    out[6 * NPIX + p] = a6;
    out[7 * NPIX + p] = a7;
}

// ---------------------------------------------------------------------------
// Entry point
// ---------------------------------------------------------------------------
extern "C" void kernel_launch(void* const* d_in, const int* in_sizes, int n_in,
                              void* d_out, int out_size)
{
    const float* sensor_data = (const float*)d_in[0];   // (4,2,128,2048) f32
    const int*   sensor_xy   = (const int*)d_in[1];     // (128,2) i32
    float*       out         = (float*)d_out;           // (4,2,512,512) f32

    das_transpose_kernel<<<(NSENS * NT + 255) / 256, 256>>>(sensor_data);

    dim3 block(256);
    dim3 grid(NYg / 16, NXg / 16);
    das_main_kernel<<<grid, block>>>(sensor_xy, out);
}